// round 5
// baseline (speedup 1.0000x reference)
#include <cuda_runtime.h>
#include <cstdint>

// Problem constants
#define NB   65536
#define SQ   9
#define DM   20
#define NH   4
#define DHD  5
#define DFF  512
#define EPSV 1e-5f

typedef unsigned long long u64;

// 47 MB scratch for y = LN1(attn_out + x)
__device__ __align__(16) float g_y[(size_t)NB * SQ * DM];

// ---------------- f32x2 helpers (Blackwell packed fp32) ----------------
__device__ __forceinline__ u64 fma2(u64 a, u64 b, u64 c) {
    u64 d;
    asm("fma.rn.f32x2 %0, %1, %2, %3;" : "=l"(d) : "l"(a), "l"(b), "l"(c));
    return d;
}
__device__ __forceinline__ u64 add2(u64 a, u64 b) {
    u64 d;
    asm("add.rn.f32x2 %0, %1, %2;" : "=l"(d) : "l"(a), "l"(b));
    return d;
}
__device__ __forceinline__ float2 unpack2(u64 a) {
    float2 r;
    asm("mov.b64 {%0, %1}, %2;" : "=f"(r.x), "=f"(r.y) : "l"(a));
    return r;
}
__device__ __forceinline__ u64 pack2(float lo, float hi) {
    u64 d;
    asm("mov.b64 %0, {%1, %2};" : "=l"(d)
        : "r"(__float_as_uint(lo)), "r"(__float_as_uint(hi)));
    return d;
}

// ======================================================================
// Kernel 1: QKV + attention + quirky merge + Wo + residual + LN1 -> g_y
// 16 batches per block, 1 thread per (batch, s) row. 144 threads.
// ======================================================================
#define GB 16
#define T1 (GB * SQ)  // 144

__global__ void __launch_bounds__(T1) k_attn(
    const float* __restrict__ X,
    const float* __restrict__ Wq, const float* __restrict__ bq,
    const float* __restrict__ Wk, const float* __restrict__ bk,
    const float* __restrict__ Wv, const float* __restrict__ bv,
    const float* __restrict__ Wo, const float* __restrict__ bo,
    const float* __restrict__ g1, const float* __restrict__ b1)
{
    __shared__ __align__(16) float sWq[DM * DM];
    __shared__ __align__(16) float sWk[DM * DM];
    __shared__ __align__(16) float sWv[DM * DM];
    __shared__ __align__(16) float sWo[DM * DM];
    __shared__ float sb[6][DM];  // bq,bk,bv,bo,g1,b1
    __shared__ __align__(16) float sK[GB][SQ][DM];
    __shared__ __align__(16) float sV[GB][SQ][DM];
    __shared__ __align__(16) float sM[GB][SQ * DM];

    const int tid = threadIdx.x;
    for (int i = tid; i < DM * DM; i += T1) {
        sWq[i] = Wq[i]; sWk[i] = Wk[i]; sWv[i] = Wv[i]; sWo[i] = Wo[i];
    }
    if (tid < DM) {
        sb[0][tid] = bq[tid]; sb[1][tid] = bk[tid]; sb[2][tid] = bv[tid];
        sb[3][tid] = bo[tid]; sb[4][tid] = g1[tid]; sb[5][tid] = b1[tid];
    }

    const int bl = tid / SQ;
    const int s  = tid - bl * SQ;
    const size_t row = (size_t)(blockIdx.x * GB + bl) * SQ + s;

    // Load x row (20 floats, 16B aligned since 80 % 16 == 0)
    float x[DM];
    {
        const float4* xr = (const float4*)(X + row * DM);
        #pragma unroll
        for (int i = 0; i < 5; i++) {
            float4 t = xr[i];
            x[4*i] = t.x; x[4*i+1] = t.y; x[4*i+2] = t.z; x[4*i+3] = t.w;
        }
    }
    __syncthreads();

    // q, k, v rows
    float q[DM], kk[DM], vv[DM];
    #pragma unroll
    for (int d = 0; d < DM; d++) { q[d] = sb[0][d]; kk[d] = sb[1][d]; vv[d] = sb[2][d]; }
    #pragma unroll
    for (int kd = 0; kd < DM; kd++) {
        const float xv = x[kd];
        #pragma unroll
        for (int d = 0; d < DM; d++) {
            q[d]  = fmaf(xv, sWq[kd * DM + d], q[d]);
            kk[d] = fmaf(xv, sWk[kd * DM + d], kk[d]);
            vv[d] = fmaf(xv, sWv[kd * DM + d], vv[d]);
        }
    }
    #pragma unroll
    for (int d = 0; d < DM; d++) { sK[bl][s][d] = kk[d]; sV[bl][s][d] = vv[d]; }
    __syncthreads();

    // Attention per head for this query row; write into merged buffer with
    // the reference's transpose(0,1,3,2).reshape quirk:
    //   flat f = h*45 + dh*9 + s  ->  merged[f/20][f%20]
    #pragma unroll
    for (int h = 0; h < NH; h++) {
        float sc[SQ];
        float mx = -1e30f;
        #pragma unroll
        for (int j = 0; j < SQ; j++) {
            float a = 0.f;
            #pragma unroll
            for (int dh = 0; dh < DHD; dh++)
                a = fmaf(q[h * DHD + dh], sK[bl][j][h * DHD + dh], a);
            a *= (1.0f / 3.0f);
            sc[j] = a;
            mx = fmaxf(mx, a);
        }
        float den = 0.f;
        #pragma unroll
        for (int j = 0; j < SQ; j++) { sc[j] = __expf(sc[j] - mx); den += sc[j]; }
        const float inv = 1.0f / den;
        float ctx[DHD] = {0.f, 0.f, 0.f, 0.f, 0.f};
        #pragma unroll
        for (int j = 0; j < SQ; j++) {
            const float p = sc[j];
            #pragma unroll
            for (int dh = 0; dh < DHD; dh++)
                ctx[dh] = fmaf(p, sV[bl][j][h * DHD + dh], ctx[dh]);
        }
        #pragma unroll
        for (int dh = 0; dh < DHD; dh++)
            sM[bl][h * 45 + dh * 9 + s] = ctx[dh] * inv;
    }
    __syncthreads();

    // attn_out = merged_row @ Wo + bo ; residual ; LN1
    float ao[DM];
    #pragma unroll
    for (int d = 0; d < DM; d++) ao[d] = sb[3][d];
    #pragma unroll
    for (int kd = 0; kd < DM; kd++) {
        const float m = sM[bl][s * DM + kd];
        #pragma unroll
        for (int d = 0; d < DM; d++) ao[d] = fmaf(m, sWo[kd * DM + d], ao[d]);
    }
    float r[DM];
    float mean = 0.f;
    #pragma unroll
    for (int d = 0; d < DM; d++) { r[d] = ao[d] + x[d]; mean += r[d]; }
    mean *= (1.0f / 20.0f);
    float var = 0.f;
    #pragma unroll
    for (int d = 0; d < DM; d++) { const float t = r[d] - mean; var = fmaf(t, t, var); }
    var *= (1.0f / 20.0f);
    const float rstd = rsqrtf(var + EPSV);

    float4* yo = (float4*)(g_y + row * DM);
    #pragma unroll
    for (int i = 0; i < 5; i++) {
        float4 t;
        t.x = (r[4*i+0] - mean) * rstd * sb[4][4*i+0] + sb[5][4*i+0];
        t.y = (r[4*i+1] - mean) * rstd * sb[4][4*i+1] + sb[5][4*i+1];
        t.z = (r[4*i+2] - mean) * rstd * sb[4][4*i+2] + sb[5][4*i+2];
        t.w = (r[4*i+3] - mean) * rstd * sb[4][4*i+3] + sb[5][4*i+3];
        yo[i] = t;
    }
}

// ======================================================================
// Kernel 2: FFN (relu(y@W1)@W2) + residual + LN2 -> out
// 256 threads, 2 rows/thread, 512 rows/block. f32x2 packed FMA.
// Dynamic shared: W1^T [512][20] + W2 [512][20] + g2 + b2 = 82,080 B
// ======================================================================
#define T2 256
#define RPB 512
#define SMEM2 ((DFF * DM * 2 + 2 * DM) * 4)

__device__ __forceinline__ void ln2_store(const u64* yp, const u64* op,
                                          const float* sg2, const float* sb2,
                                          float* outrow)
{
    float r[DM];
    float mean = 0.f;
    #pragma unroll
    for (int p = 0; p < 10; p++) {
        float2 yv = unpack2(yp[p]);
        float2 fv = unpack2(op[p]);
        r[2*p]   = yv.x + fv.x;
        r[2*p+1] = yv.y + fv.y;
        mean += r[2*p] + r[2*p+1];
    }
    mean *= (1.0f / 20.0f);
    float var = 0.f;
    #pragma unroll
    for (int d = 0; d < DM; d++) { const float t = r[d] - mean; var = fmaf(t, t, var); }
    var *= (1.0f / 20.0f);
    const float rstd = rsqrtf(var + EPSV);
    float4* o4 = (float4*)outrow;
    #pragma unroll
    for (int i = 0; i < 5; i++) {
        float4 t;
        t.x = (r[4*i+0] - mean) * rstd * sg2[4*i+0] + sb2[4*i+0];
        t.y = (r[4*i+1] - mean) * rstd * sg2[4*i+1] + sb2[4*i+1];
        t.z = (r[4*i+2] - mean) * rstd * sg2[4*i+2] + sb2[4*i+2];
        t.w = (r[4*i+3] - mean) * rstd * sg2[4*i+3] + sb2[4*i+3];
        o4[i] = t;
    }
}

__global__ void __launch_bounds__(T2) k_ffn(
    const float* __restrict__ W1, const float* __restrict__ W2,
    const float* __restrict__ g2, const float* __restrict__ b2,
    float* __restrict__ Out)
{
    extern __shared__ __align__(16) float sm[];
    float* sW1t = sm;                 // [512][20], transposed: row j = W1[:, j]
    float* sW2  = sm + DFF * DM;      // [512][20], as stored
    float* sg2  = sm + 2 * DFF * DM;
    float* sb2  = sg2 + DM;

    const int tid = threadIdx.x;
    for (int i = tid; i < DFF * DM; i += T2) {
        const int k = i / DFF;        // W1 is [20][512] row-major
        const int j = i - k * DFF;
        sW1t[j * DM + k] = W1[i];
        sW2[i] = W2[i];               // W2 is [512][20] row-major, direct copy
    }
    if (tid < DM) { sg2[tid] = g2[tid]; sb2[tid] = b2[tid]; }
    __syncthreads();

    const size_t r0 = (size_t)blockIdx.x * RPB + (size_t)tid * 2;

    // Load two y rows as packed f32x2 pairs (rows are 80B, 16B aligned)
    u64 ya[10], yb[10];
    {
        const ulonglong2* y0 = (const ulonglong2*)(g_y + r0 * DM);
        const ulonglong2* y1 = (const ulonglong2*)(g_y + (r0 + 1) * DM);
        #pragma unroll
        for (int p = 0; p < 5; p++) {
            ulonglong2 a = y0[p]; ya[2*p] = a.x; ya[2*p+1] = a.y;
            ulonglong2 b = y1[p]; yb[2*p] = b.x; yb[2*p+1] = b.y;
        }
    }

    u64 oa[10], ob[10];
    #pragma unroll
    for (int p = 0; p < 10; p++) { oa[p] = 0ULL; ob[p] = 0ULL; }

    const ulonglong2* w1base = (const ulonglong2*)sW1t;
    const ulonglong2* w2base = (const ulonglong2*)sW2;

    #pragma unroll 2
    for (int j = 0; j < DFF; j++) {
        const ulonglong2* w1p = w1base + j * 5;
        u64 a0 = 0ULL, a1 = 0ULL, b0 = 0ULL, b1 = 0ULL;
        #pragma unroll
        for (int p = 0; p < 5; p++) {
            const ulonglong2 w = w1p[p];         // LDS.128 broadcast
            a0 = fma2(ya[2*p],   w.x, a0);
            a1 = fma2(ya[2*p+1], w.y, a1);
            b0 = fma2(yb[2*p],   w.x, b0);
            b1 = fma2(yb[2*p+1], w.y, b1);
        }
        const float2 af = unpack2(add2(a0, a1));
        const float2 bf = unpack2(add2(b0, b1));
        const float ha = fmaxf(af.x + af.y, 0.f);   // relu, no bias on W1
        const float hb = fmaxf(bf.x + bf.y, 0.f);
        const u64 hha = pack2(ha, ha);
        const u64 hhb = pack2(hb, hb);

        const ulonglong2* w2p = w2base + j * 5;
        #pragma unroll
        for (int p = 0; p < 5; p++) {
            const ulonglong2 w = w2p[p];         // LDS.128 broadcast
            oa[2*p]   = fma2(hha, w.x, oa[2*p]);
            oa[2*p+1] = fma2(hha, w.y, oa[2*p+1]);
            ob[2*p]   = fma2(hhb, w.x, ob[2*p]);
            ob[2*p+1] = fma2(hhb, w.y, ob[2*p+1]);
        }
    }

    ln2_store(ya, oa, sg2, sb2, Out + r0 * DM);
    ln2_store(yb, ob, sg2, sb2, Out + (r0 + 1) * DM);
}

// ======================================================================
// Launch
// ======================================================================
extern "C" void kernel_launch(void* const* d_in, const int* in_sizes, int n_in,
                              void* d_out, int out_size)
{
    (void)in_sizes; (void)n_in; (void)out_size;
    const float* X  = (const float*)d_in[0];
    const float* Wq = (const float*)d_in[1];
    const float* bq = (const float*)d_in[2];
    const float* Wk = (const float*)d_in[3];
    const float* bk = (const float*)d_in[4];
    const float* Wv = (const float*)d_in[5];
    const float* bv = (const float*)d_in[6];
    const float* Wo = (const float*)d_in[7];
    const float* bo = (const float*)d_in[8];
    const float* g1 = (const float*)d_in[9];
    const float* b1 = (const float*)d_in[10];
    const float* W1 = (const float*)d_in[11];
    const float* W2 = (const float*)d_in[12];
    const float* g2 = (const float*)d_in[13];
    const float* b2 = (const float*)d_in[14];
    float* Out = (float*)d_out;

    cudaFuncSetAttribute(k_ffn, cudaFuncAttributeMaxDynamicSharedMemorySize, SMEM2);

    k_attn<<<NB / GB, T1>>>(X, Wq, bq, Wk, bk, Wv, bv, Wo, bo, g1, b1);
    k_ffn<<<(NB * SQ) / RPB, T2, SMEM2>>>(W1, W2, g2, b2, Out);
}

// round 6
// speedup vs baseline: 1.0012x; 1.0012x over previous
#include <cuda_runtime.h>
#include <cstdint>

// Problem constants
#define NB   65536
#define SQ   9
#define DM   20
#define NH   4
#define DHD  5
#define DFF  512
#define EPSV 1e-5f

typedef unsigned long long u64;

// 47 MB scratch for y = LN1(attn_out + x)
__device__ __align__(16) float g_y[(size_t)NB * SQ * DM];

// ---------------- f32x2 helpers (Blackwell packed fp32) ----------------
__device__ __forceinline__ u64 fma2(u64 a, u64 b, u64 c) {
    u64 d;
    asm("fma.rn.f32x2 %0, %1, %2, %3;" : "=l"(d) : "l"(a), "l"(b), "l"(c));
    return d;
}
__device__ __forceinline__ u64 add2(u64 a, u64 b) {
    u64 d;
    asm("add.rn.f32x2 %0, %1, %2;" : "=l"(d) : "l"(a), "l"(b));
    return d;
}
__device__ __forceinline__ float2 unpack2(u64 a) {
    float2 r;
    asm("mov.b64 {%0, %1}, %2;" : "=f"(r.x), "=f"(r.y) : "l"(a));
    return r;
}
__device__ __forceinline__ u64 pack2(float lo, float hi) {
    u64 d;
    asm("mov.b64 %0, {%1, %2};" : "=l"(d)
        : "r"(__float_as_uint(lo)), "r"(__float_as_uint(hi)));
    return d;
}

// ======================================================================
// Kernel 1: QKV + attention + quirky merge + Wo + residual + LN1 -> g_y
// 16 batches per block, 1 thread per (batch, s) row. 144 threads.
// ======================================================================
#define GB 16
#define T1 (GB * SQ)  // 144

__global__ void __launch_bounds__(T1) k_attn(
    const float* __restrict__ X,
    const float* __restrict__ Wq, const float* __restrict__ bq,
    const float* __restrict__ Wk, const float* __restrict__ bk,
    const float* __restrict__ Wv, const float* __restrict__ bv,
    const float* __restrict__ Wo, const float* __restrict__ bo,
    const float* __restrict__ g1, const float* __restrict__ b1)
{
    __shared__ __align__(16) float sWq[DM * DM];
    __shared__ __align__(16) float sWk[DM * DM];
    __shared__ __align__(16) float sWv[DM * DM];
    __shared__ __align__(16) float sWo[DM * DM];
    __shared__ float sb[6][DM];  // bq,bk,bv,bo,g1,b1
    __shared__ __align__(16) float sK[GB][SQ][DM];
    __shared__ __align__(16) float sV[GB][SQ][DM];
    __shared__ __align__(16) float sM[GB][SQ * DM];

    const int tid = threadIdx.x;
    for (int i = tid; i < DM * DM; i += T1) {
        sWq[i] = Wq[i]; sWk[i] = Wk[i]; sWv[i] = Wv[i]; sWo[i] = Wo[i];
    }
    if (tid < DM) {
        sb[0][tid] = bq[tid]; sb[1][tid] = bk[tid]; sb[2][tid] = bv[tid];
        sb[3][tid] = bo[tid]; sb[4][tid] = g1[tid]; sb[5][tid] = b1[tid];
    }

    const int bl = tid / SQ;
    const int s  = tid - bl * SQ;
    const size_t row = (size_t)(blockIdx.x * GB + bl) * SQ + s;

    // Load x row (20 floats, 16B aligned since 80 % 16 == 0)
    float x[DM];
    {
        const float4* xr = (const float4*)(X + row * DM);
        #pragma unroll
        for (int i = 0; i < 5; i++) {
            float4 t = xr[i];
            x[4*i] = t.x; x[4*i+1] = t.y; x[4*i+2] = t.z; x[4*i+3] = t.w;
        }
    }
    __syncthreads();

    // q, k, v rows
    float q[DM], kk[DM], vv[DM];
    #pragma unroll
    for (int d = 0; d < DM; d++) { q[d] = sb[0][d]; kk[d] = sb[1][d]; vv[d] = sb[2][d]; }
    #pragma unroll
    for (int kd = 0; kd < DM; kd++) {
        const float xv = x[kd];
        #pragma unroll
        for (int d = 0; d < DM; d++) {
            q[d]  = fmaf(xv, sWq[kd * DM + d], q[d]);
            kk[d] = fmaf(xv, sWk[kd * DM + d], kk[d]);
            vv[d] = fmaf(xv, sWv[kd * DM + d], vv[d]);
        }
    }
    #pragma unroll
    for (int d = 0; d < DM; d++) { sK[bl][s][d] = kk[d]; sV[bl][s][d] = vv[d]; }
    __syncthreads();

    // Attention per head for this query row; write into merged buffer with
    // the reference's transpose(0,1,3,2).reshape quirk:
    //   flat f = h*45 + dh*9 + s  ->  merged[f/20][f%20]
    #pragma unroll
    for (int h = 0; h < NH; h++) {
        float sc[SQ];
        float mx = -1e30f;
        #pragma unroll
        for (int j = 0; j < SQ; j++) {
            float a = 0.f;
            #pragma unroll
            for (int dh = 0; dh < DHD; dh++)
                a = fmaf(q[h * DHD + dh], sK[bl][j][h * DHD + dh], a);
            a *= (1.0f / 3.0f);
            sc[j] = a;
            mx = fmaxf(mx, a);
        }
        float den = 0.f;
        #pragma unroll
        for (int j = 0; j < SQ; j++) { sc[j] = __expf(sc[j] - mx); den += sc[j]; }
        const float inv = 1.0f / den;
        float ctx[DHD] = {0.f, 0.f, 0.f, 0.f, 0.f};
        #pragma unroll
        for (int j = 0; j < SQ; j++) {
            const float p = sc[j];
            #pragma unroll
            for (int dh = 0; dh < DHD; dh++)
                ctx[dh] = fmaf(p, sV[bl][j][h * DHD + dh], ctx[dh]);
        }
        #pragma unroll
        for (int dh = 0; dh < DHD; dh++)
            sM[bl][h * 45 + dh * 9 + s] = ctx[dh] * inv;
    }
    __syncthreads();

    // attn_out = merged_row @ Wo + bo ; residual ; LN1
    float ao[DM];
    #pragma unroll
    for (int d = 0; d < DM; d++) ao[d] = sb[3][d];
    #pragma unroll
    for (int kd = 0; kd < DM; kd++) {
        const float m = sM[bl][s * DM + kd];
        #pragma unroll
        for (int d = 0; d < DM; d++) ao[d] = fmaf(m, sWo[kd * DM + d], ao[d]);
    }
    float r[DM];
    float mean = 0.f;
    #pragma unroll
    for (int d = 0; d < DM; d++) { r[d] = ao[d] + x[d]; mean += r[d]; }
    mean *= (1.0f / 20.0f);
    float var = 0.f;
    #pragma unroll
    for (int d = 0; d < DM; d++) { const float t = r[d] - mean; var = fmaf(t, t, var); }
    var *= (1.0f / 20.0f);
    const float rstd = rsqrtf(var + EPSV);

    float4* yo = (float4*)(g_y + row * DM);
    #pragma unroll
    for (int i = 0; i < 5; i++) {
        float4 t;
        t.x = (r[4*i+0] - mean) * rstd * sb[4][4*i+0] + sb[5][4*i+0];
        t.y = (r[4*i+1] - mean) * rstd * sb[4][4*i+1] + sb[5][4*i+1];
        t.z = (r[4*i+2] - mean) * rstd * sb[4][4*i+2] + sb[5][4*i+2];
        t.w = (r[4*i+3] - mean) * rstd * sb[4][4*i+3] + sb[5][4*i+3];
        yo[i] = t;
    }
}

// ======================================================================
// Kernel 2: FFN (relu(y@W1)@W2) + residual + LN2 -> out
// 256 threads, 2 rows/thread, 512 rows/block. f32x2 packed FMA.
// Dynamic shared: W1^T [512][20] + W2 [512][20] + g2 + b2 = 82,080 B
// ======================================================================
#define T2 256
#define RPB 512
#define SMEM2 ((DFF * DM * 2 + 2 * DM) * 4)

__device__ __forceinline__ void ln2_store(const u64* yp, const u64* op,
                                          const float* sg2, const float* sb2,
                                          float* outrow)
{
    float r[DM];
    float mean = 0.f;
    #pragma unroll
    for (int p = 0; p < 10; p++) {
        float2 yv = unpack2(yp[p]);
        float2 fv = unpack2(op[p]);
        r[2*p]   = yv.x + fv.x;
        r[2*p+1] = yv.y + fv.y;
        mean += r[2*p] + r[2*p+1];
    }
    mean *= (1.0f / 20.0f);
    float var = 0.f;
    #pragma unroll
    for (int d = 0; d < DM; d++) { const float t = r[d] - mean; var = fmaf(t, t, var); }
    var *= (1.0f / 20.0f);
    const float rstd = rsqrtf(var + EPSV);
    float4* o4 = (float4*)outrow;
    #pragma unroll
    for (int i = 0; i < 5; i++) {
        float4 t;
        t.x = (r[4*i+0] - mean) * rstd * sg2[4*i+0] + sb2[4*i+0];
        t.y = (r[4*i+1] - mean) * rstd * sg2[4*i+1] + sb2[4*i+1];
        t.z = (r[4*i+2] - mean) * rstd * sg2[4*i+2] + sb2[4*i+2];
        t.w = (r[4*i+3] - mean) * rstd * sg2[4*i+3] + sb2[4*i+3];
        o4[i] = t;
    }
}

__global__ void __launch_bounds__(T2) k_ffn(
    const float* __restrict__ W1, const float* __restrict__ W2,
    const float* __restrict__ g2, const float* __restrict__ b2,
    float* __restrict__ Out)
{
    extern __shared__ __align__(16) float sm[];
    float* sW1t = sm;                 // [512][20], transposed: row j = W1[:, j]
    float* sW2  = sm + DFF * DM;      // [512][20], as stored
    float* sg2  = sm + 2 * DFF * DM;
    float* sb2  = sg2 + DM;

    const int tid = threadIdx.x;
    for (int i = tid; i < DFF * DM; i += T2) {
        const int k = i / DFF;        // W1 is [20][512] row-major
        const int j = i - k * DFF;
        sW1t[j * DM + k] = W1[i];
        sW2[i] = W2[i];               // W2 is [512][20] row-major, direct copy
    }
    if (tid < DM) { sg2[tid] = g2[tid]; sb2[tid] = b2[tid]; }
    __syncthreads();

    const size_t r0 = (size_t)blockIdx.x * RPB + (size_t)tid * 2;

    // Load two y rows as packed f32x2 pairs (rows are 80B, 16B aligned)
    u64 ya[10], yb[10];
    {
        const ulonglong2* y0 = (const ulonglong2*)(g_y + r0 * DM);
        const ulonglong2* y1 = (const ulonglong2*)(g_y + (r0 + 1) * DM);
        #pragma unroll
        for (int p = 0; p < 5; p++) {
            ulonglong2 a = y0[p]; ya[2*p] = a.x; ya[2*p+1] = a.y;
            ulonglong2 b = y1[p]; yb[2*p] = b.x; yb[2*p+1] = b.y;
        }
    }

    u64 oa[10], ob[10];
    #pragma unroll
    for (int p = 0; p < 10; p++) { oa[p] = 0ULL; ob[p] = 0ULL; }

    const ulonglong2* w1base = (const ulonglong2*)sW1t;
    const ulonglong2* w2base = (const ulonglong2*)sW2;

    #pragma unroll 2
    for (int j = 0; j < DFF; j++) {
        const ulonglong2* w1p = w1base + j * 5;
        u64 a0 = 0ULL, a1 = 0ULL, b0 = 0ULL, b1 = 0ULL;
        #pragma unroll
        for (int p = 0; p < 5; p++) {
            const ulonglong2 w = w1p[p];         // LDS.128 broadcast
            a0 = fma2(ya[2*p],   w.x, a0);
            a1 = fma2(ya[2*p+1], w.y, a1);
            b0 = fma2(yb[2*p],   w.x, b0);
            b1 = fma2(yb[2*p+1], w.y, b1);
        }
        const float2 af = unpack2(add2(a0, a1));
        const float2 bf = unpack2(add2(b0, b1));
        const float ha = fmaxf(af.x + af.y, 0.f);   // relu, no bias on W1
        const float hb = fmaxf(bf.x + bf.y, 0.f);
        const u64 hha = pack2(ha, ha);
        const u64 hhb = pack2(hb, hb);

        const ulonglong2* w2p = w2base + j * 5;
        #pragma unroll
        for (int p = 0; p < 5; p++) {
            const ulonglong2 w = w2p[p];         // LDS.128 broadcast
            oa[2*p]   = fma2(hha, w.x, oa[2*p]);
            oa[2*p+1] = fma2(hha, w.y, oa[2*p+1]);
            ob[2*p]   = fma2(hhb, w.x, ob[2*p]);
            ob[2*p+1] = fma2(hhb, w.y, ob[2*p+1]);
        }
    }

    ln2_store(ya, oa, sg2, sb2, Out + r0 * DM);
    ln2_store(yb, ob, sg2, sb2, Out + (r0 + 1) * DM);
}

// ======================================================================
// Launch
// ======================================================================
extern "C" void kernel_launch(void* const* d_in, const int* in_sizes, int n_in,
                              void* d_out, int out_size)
{
    (void)in_sizes; (void)n_in; (void)out_size;
    const float* X  = (const float*)d_in[0];
    const float* Wq = (const float*)d_in[1];
    const float* bq = (const float*)d_in[2];
    const float* Wk = (const float*)d_in[3];
    const float* bk = (const float*)d_in[4];
    const float* Wv = (const float*)d_in[5];
    const float* bv = (const float*)d_in[6];
    const float* Wo = (const float*)d_in[7];
    const float* bo = (const float*)d_in[8];
    const float* g1 = (const float*)d_in[9];
    const float* b1 = (const float*)d_in[10];
    const float* W1 = (const float*)d_in[11];
    const float* W2 = (const float*)d_in[12];
    const float* g2 = (const float*)d_in[13];
    const float* b2 = (const float*)d_in[14];
    float* Out = (float*)d_out;

    cudaFuncSetAttribute(k_ffn, cudaFuncAttributeMaxDynamicSharedMemorySize, SMEM2);

    k_attn<<<NB / GB, T1>>>(X, Wq, bq, Wk, bk, Wv, bv, Wo, bo, g1, b1);
    k_ffn<<<(NB * SQ) / RPB, T2, SMEM2>>>(W1, W2, g2, b2, Out);
}

// round 7
// speedup vs baseline: 1.1793x; 1.1779x over previous
#include <cuda_runtime.h>
#include <cstdint>

// Problem constants
#define NB   65536
#define SQ   9
#define DM   20
#define NH   4
#define DHD  5
#define DFF  512
#define EPSV 1e-5f

typedef unsigned long long u64;

// 47 MB scratch for y = LN1(attn_out + x)
__device__ __align__(16) float g_y[(size_t)NB * SQ * DM];

// ---------------- f32x2 helpers (Blackwell packed fp32) ----------------
__device__ __forceinline__ u64 fma2(u64 a, u64 b, u64 c) {
    u64 d;
    asm("fma.rn.f32x2 %0, %1, %2, %3;" : "=l"(d) : "l"(a), "l"(b), "l"(c));
    return d;
}
__device__ __forceinline__ u64 mul2(u64 a, u64 b) {
    u64 d;
    asm("mul.rn.f32x2 %0, %1, %2;" : "=l"(d) : "l"(a), "l"(b));
    return d;
}
__device__ __forceinline__ float2 unpack2(u64 a) {
    float2 r;
    asm("mov.b64 {%0, %1}, %2;" : "=f"(r.x), "=f"(r.y) : "l"(a));
    return r;
}
__device__ __forceinline__ u64 pack2(float lo, float hi) {
    u64 d;
    asm("mov.b64 %0, {%1, %2};" : "=l"(d)
        : "r"(__float_as_uint(lo)), "r"(__float_as_uint(hi)));
    return d;
}

// ======================================================================
// Kernel 1: QKV + attention + quirky merge + Wo + residual + LN1 -> g_y
// 16 batches per block, 1 thread per (batch, s) row. 144 threads.
// QKV and Wo matmuls use packed f32x2 FMA (splat-x against row-major
// weight pairs, which are naturally contiguous).
// ======================================================================
#define GB 16
#define T1 (GB * SQ)  // 144

__global__ void __launch_bounds__(T1) k_attn(
    const float* __restrict__ X,
    const float* __restrict__ Wq, const float* __restrict__ bq,
    const float* __restrict__ Wk, const float* __restrict__ bk,
    const float* __restrict__ Wv, const float* __restrict__ bv,
    const float* __restrict__ Wo, const float* __restrict__ bo,
    const float* __restrict__ g1, const float* __restrict__ b1)
{
    __shared__ __align__(16) float sWq[DM * DM];
    __shared__ __align__(16) float sWk[DM * DM];
    __shared__ __align__(16) float sWv[DM * DM];
    __shared__ __align__(16) float sWo[DM * DM];
    __shared__ __align__(16) float sb[6][DM];  // bq,bk,bv,bo,g1,b1
    __shared__ __align__(16) float sK[GB][SQ][DM];
    __shared__ __align__(16) float sV[GB][SQ][DM];
    __shared__ __align__(16) float sM[GB][SQ * DM];

    const int tid = threadIdx.x;
    for (int i = tid; i < DM * DM; i += T1) {
        sWq[i] = Wq[i]; sWk[i] = Wk[i]; sWv[i] = Wv[i]; sWo[i] = Wo[i];
    }
    if (tid < DM) {
        sb[0][tid] = bq[tid]; sb[1][tid] = bk[tid]; sb[2][tid] = bv[tid];
        sb[3][tid] = bo[tid]; sb[4][tid] = g1[tid]; sb[5][tid] = b1[tid];
    }

    const int bl = tid / SQ;
    const int s  = tid - bl * SQ;
    const size_t row = (size_t)(blockIdx.x * GB + bl) * SQ + s;

    // Load x row (20 floats, 16B aligned since 80 % 16 == 0)
    float x[DM];
    {
        const float4* xr = (const float4*)(X + row * DM);
        #pragma unroll
        for (int i = 0; i < 5; i++) {
            float4 t = xr[i];
            x[4*i] = t.x; x[4*i+1] = t.y; x[4*i+2] = t.z; x[4*i+3] = t.w;
        }
    }
    __syncthreads();

    // q, k, v rows — packed f32x2 accumulators over output-dim pairs
    u64 q2[10], k2[10], v2[10];
    {
        const u64* bq2 = (const u64*)sb[0];
        const u64* bk2 = (const u64*)sb[1];
        const u64* bv2 = (const u64*)sb[2];
        #pragma unroll
        for (int p = 0; p < 10; p++) { q2[p] = bq2[p]; k2[p] = bk2[p]; v2[p] = bv2[p]; }
    }
    #pragma unroll
    for (int kd = 0; kd < DM; kd++) {
        const u64 x2 = pack2(x[kd], x[kd]);
        const ulonglong2* wq = (const ulonglong2*)(sWq + kd * DM);
        const ulonglong2* wk = (const ulonglong2*)(sWk + kd * DM);
        const ulonglong2* wv = (const ulonglong2*)(sWv + kd * DM);
        #pragma unroll
        for (int p = 0; p < 5; p++) {
            const ulonglong2 a = wq[p];
            q2[2*p]   = fma2(x2, a.x, q2[2*p]);
            q2[2*p+1] = fma2(x2, a.y, q2[2*p+1]);
            const ulonglong2 b = wk[p];
            k2[2*p]   = fma2(x2, b.x, k2[2*p]);
            k2[2*p+1] = fma2(x2, b.y, k2[2*p+1]);
            const ulonglong2 c = wv[p];
            v2[2*p]   = fma2(x2, c.x, v2[2*p]);
            v2[2*p+1] = fma2(x2, c.y, v2[2*p+1]);
        }
    }
    // store k, v rows to smem (pair layout == float layout)
    {
        u64* kp = (u64*)(&sK[bl][s][0]);
        u64* vp = (u64*)(&sV[bl][s][0]);
        #pragma unroll
        for (int p = 0; p < 10; p++) { kp[p] = k2[p]; vp[p] = v2[p]; }
    }
    float q[DM];
    #pragma unroll
    for (int p = 0; p < 10; p++) {
        float2 t = unpack2(q2[p]);
        q[2*p] = t.x; q[2*p+1] = t.y;
    }
    __syncthreads();

    // Attention per head for this query row; write into merged buffer with
    // the reference's transpose(0,1,3,2).reshape quirk:
    //   flat f = h*45 + dh*9 + s  ->  merged[f/20][f%20]
    #pragma unroll
    for (int h = 0; h < NH; h++) {
        float sc[SQ];
        float mx = -1e30f;
        #pragma unroll
        for (int j = 0; j < SQ; j++) {
            float a = 0.f;
            #pragma unroll
            for (int dh = 0; dh < DHD; dh++)
                a = fmaf(q[h * DHD + dh], sK[bl][j][h * DHD + dh], a);
            a *= (1.0f / 3.0f);
            sc[j] = a;
            mx = fmaxf(mx, a);
        }
        float den = 0.f;
        #pragma unroll
        for (int j = 0; j < SQ; j++) { sc[j] = __expf(sc[j] - mx); den += sc[j]; }
        const float inv = 1.0f / den;
        float ctx[DHD] = {0.f, 0.f, 0.f, 0.f, 0.f};
        #pragma unroll
        for (int j = 0; j < SQ; j++) {
            const float p = sc[j];
            #pragma unroll
            for (int dh = 0; dh < DHD; dh++)
                ctx[dh] = fmaf(p, sV[bl][j][h * DHD + dh], ctx[dh]);
        }
        #pragma unroll
        for (int dh = 0; dh < DHD; dh++)
            sM[bl][h * 45 + dh * 9 + s] = ctx[dh] * inv;
    }
    __syncthreads();

    // attn_out = merged_row @ Wo + bo (packed) ; residual ; LN1
    u64 ao2[10];
    {
        const u64* bo2 = (const u64*)sb[3];
        #pragma unroll
        for (int p = 0; p < 10; p++) ao2[p] = bo2[p];
    }
    #pragma unroll
    for (int kd = 0; kd < DM; kd++) {
        const float m = sM[bl][s * DM + kd];
        const u64 m2 = pack2(m, m);
        const ulonglong2* wo = (const ulonglong2*)(sWo + kd * DM);
        #pragma unroll
        for (int p = 0; p < 5; p++) {
            const ulonglong2 w = wo[p];
            ao2[2*p]   = fma2(m2, w.x, ao2[2*p]);
            ao2[2*p+1] = fma2(m2, w.y, ao2[2*p+1]);
        }
    }
    float r[DM];
    float mean = 0.f;
    #pragma unroll
    for (int p = 0; p < 10; p++) {
        float2 a = unpack2(ao2[p]);
        r[2*p]   = a.x + x[2*p];
        r[2*p+1] = a.y + x[2*p+1];
        mean += r[2*p] + r[2*p+1];
    }
    mean *= (1.0f / 20.0f);
    float var = 0.f;
    #pragma unroll
    for (int d = 0; d < DM; d++) { const float t = r[d] - mean; var = fmaf(t, t, var); }
    var *= (1.0f / 20.0f);
    const float rstd = rsqrtf(var + EPSV);

    float4* yo = (float4*)(g_y + row * DM);
    #pragma unroll
    for (int i = 0; i < 5; i++) {
        float4 t;
        t.x = (r[4*i+0] - mean) * rstd * sb[4][4*i+0] + sb[5][4*i+0];
        t.y = (r[4*i+1] - mean) * rstd * sb[4][4*i+1] + sb[5][4*i+1];
        t.z = (r[4*i+2] - mean) * rstd * sb[4][4*i+2] + sb[5][4*i+2];
        t.w = (r[4*i+3] - mean) * rstd * sb[4][4*i+3] + sb[5][4*i+3];
        yo[i] = t;
    }
}

// ======================================================================
// Kernel 2: FFN (relu(y@W1)@W2) + residual + LN2 -> out
// 256 threads, 2 rows/thread, 512 rows/block. f32x2 packed FMA.
// Manual 2-j unroll with single 10-deep chains per (row,j) and loads
// hoisted so reductions cover LDS latency.
// Dynamic shared: W1^T [512][20] + W2 [512][20] + g2 + b2 = 82,080 B
// ======================================================================
#define T2 256
#define RPB 512
#define SMEM2 ((DFF * DM * 2 + 2 * DM) * 4)

__device__ __forceinline__ void ln2_store(const u64* yp, const u64* op,
                                          const float* sg2, const float* sb2,
                                          float* outrow)
{
    float r[DM];
    float mean = 0.f;
    #pragma unroll
    for (int p = 0; p < 10; p++) {
        float2 yv = unpack2(yp[p]);
        float2 fv = unpack2(op[p]);
        r[2*p]   = yv.x + fv.x;
        r[2*p+1] = yv.y + fv.y;
        mean += r[2*p] + r[2*p+1];
    }
    mean *= (1.0f / 20.0f);
    float var = 0.f;
    #pragma unroll
    for (int d = 0; d < DM; d++) { const float t = r[d] - mean; var = fmaf(t, t, var); }
    var *= (1.0f / 20.0f);
    const float rstd = rsqrtf(var + EPSV);
    float4* o4 = (float4*)outrow;
    #pragma unroll
    for (int i = 0; i < 5; i++) {
        float4 t;
        t.x = (r[4*i+0] - mean) * rstd * sg2[4*i+0] + sb2[4*i+0];
        t.y = (r[4*i+1] - mean) * rstd * sg2[4*i+1] + sb2[4*i+1];
        t.z = (r[4*i+2] - mean) * rstd * sg2[4*i+2] + sb2[4*i+2];
        t.w = (r[4*i+3] - mean) * rstd * sg2[4*i+3] + sb2[4*i+3];
        o4[i] = t;
    }
}

// 10-deep packed dot chain: returns sum over 20 elements of y (10 u64 pairs)
// against one W1^T row held as 5 ulonglong2.
__device__ __forceinline__ float dot20(const u64* y,
                                       ulonglong2 w0, ulonglong2 w1,
                                       ulonglong2 w2, ulonglong2 w3,
                                       ulonglong2 w4)
{
    u64 a = mul2(y[0], w0.x);
    a = fma2(y[1], w0.y, a);
    a = fma2(y[2], w1.x, a);
    a = fma2(y[3], w1.y, a);
    a = fma2(y[4], w2.x, a);
    a = fma2(y[5], w2.y, a);
    a = fma2(y[6], w3.x, a);
    a = fma2(y[7], w3.y, a);
    a = fma2(y[8], w4.x, a);
    a = fma2(y[9], w4.y, a);
    float2 f = unpack2(a);
    return f.x + f.y;
}

__global__ void __launch_bounds__(T2, 2) k_ffn(
    const float* __restrict__ W1, const float* __restrict__ W2,
    const float* __restrict__ g2, const float* __restrict__ b2,
    float* __restrict__ Out)
{
    extern __shared__ __align__(16) float sm[];
    float* sW1t = sm;                 // [512][20], transposed: row j = W1[:, j]
    float* sW2  = sm + DFF * DM;      // [512][20], as stored
    float* sg2  = sm + 2 * DFF * DM;
    float* sb2  = sg2 + DM;

    const int tid = threadIdx.x;
    for (int i = tid; i < DFF * DM; i += T2) {
        const int k = i / DFF;        // W1 is [20][512] row-major
        const int j = i - k * DFF;
        sW1t[j * DM + k] = W1[i];
        sW2[i] = W2[i];               // W2 is [512][20] row-major, direct copy
    }
    if (tid < DM) { sg2[tid] = g2[tid]; sb2[tid] = b2[tid]; }
    __syncthreads();

    const size_t r0 = (size_t)blockIdx.x * RPB + (size_t)tid * 2;

    // Load two y rows as packed f32x2 pairs (rows are 80B, 16B aligned)
    u64 ya[10], yb[10];
    {
        const ulonglong2* y0 = (const ulonglong2*)(g_y + r0 * DM);
        const ulonglong2* y1 = (const ulonglong2*)(g_y + (r0 + 1) * DM);
        #pragma unroll
        for (int p = 0; p < 5; p++) {
            ulonglong2 a = y0[p]; ya[2*p] = a.x; ya[2*p+1] = a.y;
            ulonglong2 b = y1[p]; yb[2*p] = b.x; yb[2*p+1] = b.y;
        }
    }

    u64 oa[10], ob[10];
    #pragma unroll
    for (int p = 0; p < 10; p++) { oa[p] = 0ULL; ob[p] = 0ULL; }

    const ulonglong2* w1base = (const ulonglong2*)sW1t;
    const ulonglong2* w2base = (const ulonglong2*)sW2;

    #pragma unroll 1
    for (int j = 0; j < DFF; j += 2) {
        // ---- up-projection, j ----
        const ulonglong2* p1 = w1base + j * 5;
        const ulonglong2 u0 = p1[0], u1 = p1[1], u2 = p1[2], u3 = p1[3], u4 = p1[4];
        const float sa = dot20(ya, u0, u1, u2, u3, u4);
        const float sb_ = dot20(yb, u0, u1, u2, u3, u4);

        // ---- up-projection, j+1 ----
        const ulonglong2* p1b = p1 + 5;
        const ulonglong2 v0 = p1b[0], v1 = p1b[1], v2 = p1b[2], v3 = p1b[3], v4 = p1b[4];
        const float sc = dot20(ya, v0, v1, v2, v3, v4);
        const float sd = dot20(yb, v0, v1, v2, v3, v4);

        // relu + splat (alu pipe)
        const float ha = fmaxf(sa, 0.f), hb = fmaxf(sb_, 0.f);
        const float hc = fmaxf(sc, 0.f), hd = fmaxf(sd, 0.f);
        const u64 hha = pack2(ha, ha), hhb = pack2(hb, hb);
        const u64 hhc = pack2(hc, hc), hhd = pack2(hd, hd);

        // ---- down-projection, j ----
        const ulonglong2* q1 = w2base + j * 5;
        #pragma unroll
        for (int p = 0; p < 5; p++) {
            const ulonglong2 w = q1[p];
            oa[2*p]   = fma2(hha, w.x, oa[2*p]);
            oa[2*p+1] = fma2(hha, w.y, oa[2*p+1]);
            ob[2*p]   = fma2(hhb, w.x, ob[2*p]);
            ob[2*p+1] = fma2(hhb, w.y, ob[2*p+1]);
        }
        // ---- down-projection, j+1 ----
        const ulonglong2* q2 = q1 + 5;
        #pragma unroll
        for (int p = 0; p < 5; p++) {
            const ulonglong2 w = q2[p];
            oa[2*p]   = fma2(hhc, w.x, oa[2*p]);
            oa[2*p+1] = fma2(hhc, w.y, oa[2*p+1]);
            ob[2*p]   = fma2(hhd, w.x, ob[2*p]);
            ob[2*p+1] = fma2(hhd, w.y, ob[2*p+1]);
        }
    }

    ln2_store(ya, oa, sg2, sb2, Out + r0 * DM);
    ln2_store(yb, ob, sg2, sb2, Out + (r0 + 1) * DM);
}

// ======================================================================
// Launch
// ======================================================================
extern "C" void kernel_launch(void* const* d_in, const int* in_sizes, int n_in,
                              void* d_out, int out_size)
{
    (void)in_sizes; (void)n_in; (void)out_size;
    const float* X  = (const float*)d_in[0];
    const float* Wq = (const float*)d_in[1];
    const float* bq = (const float*)d_in[2];
    const float* Wk = (const float*)d_in[3];
    const float* bk = (const float*)d_in[4];
    const float* Wv = (const float*)d_in[5];
    const float* bv = (const float*)d_in[6];
    const float* Wo = (const float*)d_in[7];
    const float* bo = (const float*)d_in[8];
    const float* g1 = (const float*)d_in[9];
    const float* b1 = (const float*)d_in[10];
    const float* W1 = (const float*)d_in[11];
    const float* W2 = (const float*)d_in[12];
    const float* g2 = (const float*)d_in[13];
    const float* b2 = (const float*)d_in[14];
    float* Out = (float*)d_out;

    cudaFuncSetAttribute(k_ffn, cudaFuncAttributeMaxDynamicSharedMemorySize, SMEM2);

    k_attn<<<NB / GB, T1>>>(X, Wq, bq, Wk, bk, Wv, bv, Wo, bo, g1, b1);
    k_ffn<<<(NB * SQ) / RPB, T2, SMEM2>>>(W1, W2, g2, b2, Out);
}